// round 2
// baseline (speedup 1.0000x reference)
#include <cuda_runtime.h>
#include <cuda_bf16.h>

// Problem constants (from reference): C=9, H=180, W=240, B=8, N=100000
#define CC 9
#define HH 180
#define WW 240
#define BB 8
#define PLANE (WW*HH)            // 43200
#define PPITCH (WW*HH*CC)        // 388800  (polarity stride)
#define BPITCH (WW*HH*CC*2)      // 777600  (batch stride)

// Table of f(u) for u in [-1, 1], 16384 cells (16385 knots).
#define TAB_CELLS 16384
#define TAB_SCALE 8192.0f        // cells per unit

__device__ float  g_vals[TAB_CELLS + 1];
__device__ float2 g_tab[TAB_CELLS];   // (value, delta) per cell -> 1 LDG.64 per lookup

// ---------------------------------------------------------------------------
// Kernel 1: zero the output (harness poisons it with 0xAA)
// ---------------------------------------------------------------------------
__global__ void zero_out_kernel(float4* __restrict__ out, int n4) {
    int i = blockIdx.x * blockDim.x + threadIdx.x;
    if (i < n4) out[i] = make_float4(0.f, 0.f, 0.f, 0.f);
}

// ---------------------------------------------------------------------------
// Kernel 2: tabulate f(u) = MLP(u) at 16385 knots.
// 4 threads cooperate per knot (each handles 25 of the 100 hidden-2 units),
// combined with shfl. w2 is staged TRANSPOSED in shared so the inner i-loop
// reads contiguous float4 (broadcast LDS, conflict-free).
// ---------------------------------------------------------------------------
__global__ __launch_bounds__(256) void build_vals_kernel(
    const float* __restrict__ w1, const float* __restrict__ b1,
    const float* __restrict__ w2, const float* __restrict__ b2,
    const float* __restrict__ w3, const float* __restrict__ b3)
{
    __shared__ float sw2t[100 * 100];   // [j][i] transposed
    __shared__ float sw1[100], sb1[100], sb2[100], sw3[100];

    int tid = threadIdx.x;
    for (int idx = tid; idx < 10000; idx += blockDim.x) {
        int i = idx / 100, j = idx % 100;        // src is [i][j] (row-major [in,out])
        sw2t[j * 100 + i] = w2[idx];
    }
    for (int idx = tid; idx < 100; idx += blockDim.x) {
        sw1[idx] = w1[idx]; sb1[idx] = b1[idx];
        sb2[idx] = b2[idx]; sw3[idx] = w3[idx];
    }
    __syncthreads();

    int gt = blockIdx.x * blockDim.x + tid;
    int point = gt >> 2;
    int s = gt & 3;                       // which 25-unit slice of layer 2
    if (point > TAB_CELLS) point = TAB_CELLS;   // tail threads duplicate last knot

    float u = -1.0f + (float)point * (1.0f / TAB_SCALE);

    // Layer 1: 100 hidden units, kept in registers.
    float h[100];
    #pragma unroll
    for (int i = 0; i < 100; i++) {
        float z = fmaf(u, sw1[i], sb1[i]);
        h[i] = fmaxf(z, 0.1f * z);        // LeakyReLU(0.1)
    }

    // Layer 2 + 3 (partial over j = s*25 .. s*25+24), 4 dep chains for ILP.
    float acc = 0.0f;
    int j0 = s * 25;
    for (int j = j0; j < j0 + 25; j++) {
        const float4* row = (const float4*)(&sw2t[j * 100]);
        float z0 = sb2[j], z1 = 0.f, z2 = 0.f, z3 = 0.f;
        #pragma unroll
        for (int i4 = 0; i4 < 25; i4++) {
            float4 w = row[i4];
            z0 = fmaf(h[4 * i4 + 0], w.x, z0);
            z1 = fmaf(h[4 * i4 + 1], w.y, z1);
            z2 = fmaf(h[4 * i4 + 2], w.z, z2);
            z3 = fmaf(h[4 * i4 + 3], w.w, z3);
        }
        float z = (z0 + z1) + (z2 + z3);
        acc = fmaf(fmaxf(z, 0.1f * z), sw3[j], acc);
    }

    // Combine the 4 partial sums (lanes {4k..4k+3} share a point).
    acc += __shfl_xor_sync(0xFFFFFFFFu, acc, 1);
    acc += __shfl_xor_sync(0xFFFFFFFFu, acc, 2);

    if (s == 0) g_vals[point] = acc + b3[0];
}

// ---------------------------------------------------------------------------
// Kernel 3: build (value, delta) pairs so a lookup is one aligned LDG.64
// ---------------------------------------------------------------------------
__global__ void build_pairs_kernel() {
    int k = blockIdx.x * blockDim.x + threadIdx.x;
    if (k < TAB_CELLS) g_tab[k] = make_float2(g_vals[k], g_vals[k + 1] - g_vals[k]);
}

// ---------------------------------------------------------------------------
// Kernel 4: scatter. Grid-stride over events; 9 bins -> 9 RED.F32 each.
// Voxel grid (24.9 MB) is L2-resident; table (128 KB) is L1/L2-resident.
// ---------------------------------------------------------------------------
__global__ __launch_bounds__(256) void scatter_kernel(
    const float* __restrict__ t, const int* __restrict__ x,
    const int* __restrict__ y,  const int* __restrict__ p,
    float* __restrict__ out, int n_total, int n_per_b)
{
    int stride = gridDim.x * blockDim.x;
    for (int e = blockIdx.x * blockDim.x + threadIdx.x; e < n_total; e += stride) {
        float tv = __ldg(t + e);
        int b = e / n_per_b;
        int base = __ldg(x + e) + WW * __ldg(y + e) + PPITCH * __ldg(p + e) + BPITCH * b;

        // u_i = tv - i/8 ; table position = (tv+1)*8192 - 1024*i (exact integer shift)
        float pos0 = (tv + 1.0f) * TAB_SCALE;

        #pragma unroll
        for (int i = 0; i < CC; i++) {
            float pi = pos0 - 1024.0f * (float)i;    // in [0, 16384]
            int k = (int)pi;
            k = max(0, min(k, TAB_CELLS - 1));
            float frac = pi - (float)k;
            float2 c = g_tab[k];
            float val = tv * fmaf(c.y, frac, c.x);
            atomicAdd(out + base + PLANE * i, val);  // no return use -> RED.F32
        }
    }
}

// ---------------------------------------------------------------------------
// Launch
// Input order (metadata): t, w1, b1, w2, b2, w3, b3, x, y, p
// ---------------------------------------------------------------------------
extern "C" void kernel_launch(void* const* d_in, const int* in_sizes, int n_in,
                              void* d_out, int out_size) {
    const float* t  = (const float*)d_in[0];
    const float* w1 = (const float*)d_in[1];
    const float* b1 = (const float*)d_in[2];
    const float* w2 = (const float*)d_in[3];
    const float* b2 = (const float*)d_in[4];
    const float* w3 = (const float*)d_in[5];
    const float* b3 = (const float*)d_in[6];
    const int*   x  = (const int*)d_in[7];
    const int*   y  = (const int*)d_in[8];
    const int*   p  = (const int*)d_in[9];
    float* out = (float*)d_out;

    int n_total = in_sizes[0];            // B*N = 800000
    int n_per_b = n_total / BB;           // 100000

    // 1) zero output
    int n4 = out_size / 4;
    zero_out_kernel<<<(n4 + 255) / 256, 256>>>((float4*)out, n4);

    // 2) tabulate f  (16385 knots x 4 threads each)
    int tab_threads = (TAB_CELLS + 1) * 4;
    build_vals_kernel<<<(tab_threads + 255) / 256, 256>>>(w1, b1, w2, b2, w3, b3);

    // 3) build lerp pairs
    build_pairs_kernel<<<(TAB_CELLS + 255) / 256, 256>>>();

    // 4) scatter events
    int blocks = (n_total + 255) / 256;
    scatter_kernel<<<blocks, 256>>>(t, x, y, p, out, n_total, n_per_b);
}

// round 3
// speedup vs baseline: 1.1538x; 1.1538x over previous
#include <cuda_runtime.h>
#include <cuda_bf16.h>

// Problem constants: C=9, H=180, W=240, B=8, N=100000
#define CC 9
#define HH 180
#define WW 240
#define BB 8
#define PLANE (WW*HH)            // 43200
#define PPITCH (WW*HH*CC)        // 388800
#define BPITCH (WW*HH*CC*2)      // 777600

// f(u) table over u in [-1,1]: 4096 cells. Per-bin shift = 4096/16... no:
// pos = (tv+1)*2048; bin shift = 2048/8 = 256 cells (exact).
#define TAB_CELLS 4096
#define TAB_SCALE 2048.0f
#define BIN_SHIFT 256.0f

#define TAB_THREADS ((TAB_CELLS + 1) * 4)                 // 16388
#define TAB_BLOCKS  ((TAB_THREADS + 255) / 256)           // 65

__device__ float  g_vals[TAB_CELLS + 1];
__device__ float2 g_tab[TAB_CELLS];   // (value, delta) -> one LDG.64 per lookup

// ---------------------------------------------------------------------------
// Kernel A (fused): blocks [0, TAB_BLOCKS) tabulate f; remaining blocks zero
// the output (harness poisons it with 0xAA). The two parts touch disjoint
// resources (FMA pipe vs HBM writes) and overlap across SMs.
// ---------------------------------------------------------------------------
__global__ __launch_bounds__(256) void table_and_zero_kernel(
    const float* __restrict__ w1, const float* __restrict__ b1,
    const float* __restrict__ w2, const float* __restrict__ b2,
    const float* __restrict__ w3, const float* __restrict__ b3,
    float4* __restrict__ out4, int n4)
{
    __shared__ float sw2t[100 * 100];   // w2 transposed: [j][i]
    __shared__ float sw1[100], sb1[100], sb2[100], sw3[100];

    int tid = threadIdx.x;

    if (blockIdx.x >= TAB_BLOCKS) {
        // ---- zero part: grid-stride over float4 elements ----
        int nzb = gridDim.x - TAB_BLOCKS;
        int stride = nzb * 256;
        for (int i = (blockIdx.x - TAB_BLOCKS) * 256 + tid; i < n4; i += stride)
            out4[i] = make_float4(0.f, 0.f, 0.f, 0.f);
        return;
    }

    // ---- table part: 4 threads per knot (each 25 of 100 hidden-2 units) ----
    for (int idx = tid; idx < 10000; idx += 256) {
        int i = idx / 100, j = idx % 100;       // src layout [in][out]
        sw2t[j * 100 + i] = w2[idx];
    }
    for (int idx = tid; idx < 100; idx += 256) {
        sw1[idx] = w1[idx]; sb1[idx] = b1[idx];
        sb2[idx] = b2[idx]; sw3[idx] = w3[idx];
    }
    __syncthreads();

    int gt = blockIdx.x * 256 + tid;
    int point = gt >> 2;
    int s = gt & 3;
    if (point > TAB_CELLS) point = TAB_CELLS;   // tail threads duplicate last knot

    float u = -1.0f + (float)point * (1.0f / TAB_SCALE);

    // Layer 1 in registers.
    float h[100];
    #pragma unroll
    for (int i = 0; i < 100; i++) {
        float z = fmaf(u, sw1[i], sb1[i]);
        h[i] = fmaxf(z, 0.1f * z);
    }

    // Layers 2+3, partial over j = s*25 .. s*25+24; 4 dep chains for ILP.
    float acc = 0.0f;
    int j0 = s * 25;
    for (int j = j0; j < j0 + 25; j++) {
        const float4* row = (const float4*)(&sw2t[j * 100]);
        float z0 = sb2[j], z1 = 0.f, z2 = 0.f, z3 = 0.f;
        #pragma unroll
        for (int i4 = 0; i4 < 25; i4++) {
            float4 w = row[i4];
            z0 = fmaf(h[4 * i4 + 0], w.x, z0);
            z1 = fmaf(h[4 * i4 + 1], w.y, z1);
            z2 = fmaf(h[4 * i4 + 2], w.z, z2);
            z3 = fmaf(h[4 * i4 + 3], w.w, z3);
        }
        float z = (z0 + z1) + (z2 + z3);
        acc = fmaf(fmaxf(z, 0.1f * z), sw3[j], acc);
    }

    acc += __shfl_xor_sync(0xFFFFFFFFu, acc, 1);
    acc += __shfl_xor_sync(0xFFFFFFFFu, acc, 2);

    if (s == 0) g_vals[point] = acc + b3[0];
}

// ---------------------------------------------------------------------------
// Kernel B: build (value, delta) pairs -> lookup is one aligned LDG.64
// ---------------------------------------------------------------------------
__global__ void build_pairs_kernel() {
    int k = blockIdx.x * blockDim.x + threadIdx.x;
    if (k < TAB_CELLS) g_tab[k] = make_float2(g_vals[k], g_vals[k + 1] - g_vals[k]);
}

// ---------------------------------------------------------------------------
// Kernel C: scatter. 2 events/thread via vectorized loads; 18 REDs in flight.
// Pair table is 32 KB -> L1-resident. Voxel grid (24.9 MB) is L2-resident.
// ---------------------------------------------------------------------------
__global__ __launch_bounds__(256) void scatter_kernel(
    const float2* __restrict__ t2, const int2* __restrict__ x2,
    const int2* __restrict__ y2,  const int2* __restrict__ p2,
    float* __restrict__ out, int n_pairs, int n_per_b)
{
    int i = blockIdx.x * blockDim.x + threadIdx.x;
    if (i >= n_pairs) return;

    float2 tv = t2[i];
    int2 xv = x2[i];
    int2 yv = y2[i];
    int2 pv = p2[i];

    // n_per_b even => a (2i, 2i+1) pair never straddles a batch boundary.
    int b = (2 * i) / n_per_b;
    int baseA = xv.x + WW * yv.x + PPITCH * pv.x + BPITCH * b;
    int baseB = xv.y + WW * yv.y + PPITCH * pv.y + BPITCH * b;

    float posA = (tv.x + 1.0f) * TAB_SCALE;
    float posB = (tv.y + 1.0f) * TAB_SCALE;

    #pragma unroll
    for (int ibin = 0; ibin < CC; ibin++) {
        float sh = BIN_SHIFT * (float)ibin;

        float pa = posA - sh;
        int ka = (int)pa;
        ka = max(0, min(ka, TAB_CELLS - 1));
        float2 ca = g_tab[ka];
        float va = tv.x * fmaf(ca.y, pa - (float)ka, ca.x);

        float pb = posB - sh;
        int kb = (int)pb;
        kb = max(0, min(kb, TAB_CELLS - 1));
        float2 cb = g_tab[kb];
        float vb = tv.y * fmaf(cb.y, pb - (float)kb, cb.x);

        atomicAdd(out + baseA + PLANE * ibin, va);
        atomicAdd(out + baseB + PLANE * ibin, vb);
    }
}

// ---------------------------------------------------------------------------
// Launch. Input order (metadata): t, w1, b1, w2, b2, w3, b3, x, y, p
// ---------------------------------------------------------------------------
extern "C" void kernel_launch(void* const* d_in, const int* in_sizes, int n_in,
                              void* d_out, int out_size) {
    const float* t  = (const float*)d_in[0];
    const float* w1 = (const float*)d_in[1];
    const float* b1 = (const float*)d_in[2];
    const float* w2 = (const float*)d_in[3];
    const float* b2 = (const float*)d_in[4];
    const float* w3 = (const float*)d_in[5];
    const float* b3 = (const float*)d_in[6];
    const int*   x  = (const int*)d_in[7];
    const int*   y  = (const int*)d_in[8];
    const int*   p  = (const int*)d_in[9];
    float* out = (float*)d_out;

    int n_total = in_sizes[0];            // 800000
    int n_per_b = n_total / BB;           // 100000
    int n4 = out_size / 4;

    // A) fused table build + output zeroing (one launch)
    int zero_blocks = 1536;
    table_and_zero_kernel<<<TAB_BLOCKS + zero_blocks, 256>>>(
        w1, b1, w2, b2, w3, b3, (float4*)out, n4);

    // B) lerp pairs
    build_pairs_kernel<<<(TAB_CELLS + 255) / 256, 256>>>();

    // C) scatter (2 events per thread)
    int n_pairs = n_total / 2;
    scatter_kernel<<<(n_pairs + 255) / 256, 256>>>(
        (const float2*)t, (const int2*)x, (const int2*)y, (const int2*)p,
        out, n_pairs, n_per_b);
}

// round 7
// speedup vs baseline: 1.1586x; 1.0041x over previous
#include <cuda_runtime.h>
#include <cuda_bf16.h>

// Problem constants: C=9, H=180, W=240, B=8, N=100000
#define CC 9
#define HH 180
#define WW 240
#define BB 8
#define PLANE (WW*HH)            // 43200
#define PPITCH (WW*HH*CC)        // 388800
#define BPITCH (WW*HH*CC*2)      // 777600

// f(u) table over u in [-1,1]: 2048 cells.
// pos = (tv+1)*1024; per-bin shift = 1024/8 = 128 cells (exact).
#define TAB_CELLS 2048
#define TAB_SCALE 1024.0f
#define BIN_SHIFT 128.0f

__device__ float  g_vals[TAB_CELLS + 1];
__device__ float2 g_tab[TAB_CELLS];   // (value, delta) -> one LDG.64 per lookup

// ---------------------------------------------------------------------------
// Kernel 1: zero output. Minimal registers -> full occupancy -> HBM write rate.
// ---------------------------------------------------------------------------
__global__ __launch_bounds__(256) void zero_out_kernel(float4* __restrict__ out, int n4) {
    int i = blockIdx.x * blockDim.x + threadIdx.x;
    if (i < n4) out[i] = make_float4(0.f, 0.f, 0.f, 0.f);
}

// ---------------------------------------------------------------------------
// Kernel 2: tabulate f(u) at 2049 knots. 4 threads per knot (25 of the 100
// hidden-2 units each), shfl-combined. w2 staged transposed in smem so the
// inner loop reads broadcast float4.
// ---------------------------------------------------------------------------
__global__ __launch_bounds__(256) void build_vals_kernel(
    const float* __restrict__ w1, const float* __restrict__ b1,
    const float* __restrict__ w2, const float* __restrict__ b2,
    const float* __restrict__ w3, const float* __restrict__ b3)
{
    __shared__ float sw2t[100 * 100];   // [j][i] transposed
    __shared__ float sw1[100], sb1[100], sb2[100], sw3[100];

    int tid = threadIdx.x;
    for (int idx = tid; idx < 10000; idx += 256) {
        int i = idx / 100, j = idx % 100;       // src layout [in][out]
        sw2t[j * 100 + i] = w2[idx];
    }
    for (int idx = tid; idx < 100; idx += 256) {
        sw1[idx] = w1[idx]; sb1[idx] = b1[idx];
        sb2[idx] = b2[idx]; sw3[idx] = w3[idx];
    }
    __syncthreads();

    int gt = blockIdx.x * 256 + tid;
    int point = gt >> 2;
    int s = gt & 3;
    if (point > TAB_CELLS) point = TAB_CELLS;   // tail threads duplicate last knot

    float u = -1.0f + (float)point * (1.0f / TAB_SCALE);

    // Layer 1 in registers.
    float h[100];
    #pragma unroll
    for (int i = 0; i < 100; i++) {
        float z = fmaf(u, sw1[i], sb1[i]);
        h[i] = fmaxf(z, 0.1f * z);
    }

    // Layers 2+3, partial over j = s*25 .. s*25+24; 4 dep chains for ILP.
    float acc = 0.0f;
    int j0 = s * 25;
    for (int j = j0; j < j0 + 25; j++) {
        const float4* row = (const float4*)(&sw2t[j * 100]);
        float z0 = sb2[j], z1 = 0.f, z2 = 0.f, z3 = 0.f;
        #pragma unroll
        for (int i4 = 0; i4 < 25; i4++) {
            float4 w = row[i4];
            z0 = fmaf(h[4 * i4 + 0], w.x, z0);
            z1 = fmaf(h[4 * i4 + 1], w.y, z1);
            z2 = fmaf(h[4 * i4 + 2], w.z, z2);
            z3 = fmaf(h[4 * i4 + 3], w.w, z3);
        }
        float z = (z0 + z1) + (z2 + z3);
        acc = fmaf(fmaxf(z, 0.1f * z), sw3[j], acc);
    }

    acc += __shfl_xor_sync(0xFFFFFFFFu, acc, 1);
    acc += __shfl_xor_sync(0xFFFFFFFFu, acc, 2);

    if (s == 0) g_vals[point] = acc + b3[0];
}

// ---------------------------------------------------------------------------
// Kernel 3: build (value, delta) pairs -> lookup is one aligned LDG.64
// ---------------------------------------------------------------------------
__global__ void build_pairs_kernel() {
    int k = blockIdx.x * blockDim.x + threadIdx.x;
    if (k < TAB_CELLS) g_tab[k] = make_float2(g_vals[k], g_vals[k + 1] - g_vals[k]);
}

// ---------------------------------------------------------------------------
// Kernel 4: scatter. 2 events/thread via vectorized loads; 18 REDs in flight.
// Pair table (16 KB) is L1-resident. Voxel grid (24.9 MB) is L2-resident.
// ---------------------------------------------------------------------------
__global__ __launch_bounds__(256) void scatter_kernel(
    const float2* __restrict__ t2, const int2* __restrict__ x2,
    const int2* __restrict__ y2,  const int2* __restrict__ p2,
    float* __restrict__ out, int n_pairs, int n_per_b)
{
    int i = blockIdx.x * blockDim.x + threadIdx.x;
    if (i >= n_pairs) return;

    float2 tv = t2[i];
    int2 xv = x2[i];
    int2 yv = y2[i];
    int2 pv = p2[i];

    // n_per_b even => a (2i, 2i+1) pair never straddles a batch boundary.
    int b = (2 * i) / n_per_b;
    int baseA = xv.x + WW * yv.x + PPITCH * pv.x + BPITCH * b;
    int baseB = xv.y + WW * yv.y + PPITCH * pv.y + BPITCH * b;

    float posA = (tv.x + 1.0f) * TAB_SCALE;
    float posB = (tv.y + 1.0f) * TAB_SCALE;

    #pragma unroll
    for (int ibin = 0; ibin < CC; ibin++) {
        float sh = BIN_SHIFT * (float)ibin;

        float pa = posA - sh;
        int ka = (int)pa;
        ka = max(0, min(ka, TAB_CELLS - 1));
        float2 ca = g_tab[ka];
        float va = tv.x * fmaf(ca.y, pa - (float)ka, ca.x);

        float pb = posB - sh;
        int kb = (int)pb;
        kb = max(0, min(kb, TAB_CELLS - 1));
        float2 cb = g_tab[kb];
        float vb = tv.y * fmaf(cb.y, pb - (float)kb, cb.x);

        atomicAdd(out + baseA + PLANE * ibin, va);
        atomicAdd(out + baseB + PLANE * ibin, vb);
    }
}

// ---------------------------------------------------------------------------
// Launch. Input order (metadata): t, w1, b1, w2, b2, w3, b3, x, y, p
// ---------------------------------------------------------------------------
extern "C" void kernel_launch(void* const* d_in, const int* in_sizes, int n_in,
                              void* d_out, int out_size) {
    const float* t  = (const float*)d_in[0];
    const float* w1 = (const float*)d_in[1];
    const float* b1 = (const float*)d_in[2];
    const float* w2 = (const float*)d_in[3];
    const float* b2 = (const float*)d_in[4];
    const float* w3 = (const float*)d_in[5];
    const float* b3 = (const float*)d_in[6];
    const int*   x  = (const int*)d_in[7];
    const int*   y  = (const int*)d_in[8];
    const int*   p  = (const int*)d_in[9];
    float* out = (float*)d_out;

    int n_total = in_sizes[0];            // 800000
    int n_per_b = n_total / BB;           // 100000
    int n4 = out_size / 4;

    // 1) zero output (lightweight kernel -> full occupancy, HBM rate)
    zero_out_kernel<<<(n4 + 255) / 256, 256>>>((float4*)out, n4);

    // 2) tabulate f (2049 knots x 4 threads = 8196 threads, 33 blocks)
    int tab_threads = (TAB_CELLS + 1) * 4;
    build_vals_kernel<<<(tab_threads + 255) / 256, 256>>>(w1, b1, w2, b2, w3, b3);

    // 3) lerp pairs
    build_pairs_kernel<<<(TAB_CELLS + 255) / 256, 256>>>();

    // 4) scatter (2 events per thread)
    int n_pairs = n_total / 2;
    scatter_kernel<<<(n_pairs + 255) / 256, 256>>>(
        (const float2*)t, (const int2*)x, (const int2*)y, (const int2*)p,
        out, n_pairs, n_per_b);
}